// round 4
// baseline (speedup 1.0000x reference)
#include <cuda_runtime.h>
#include <cuda_bf16.h>

#define FRAME_L   1024
#define HOP       256
#define MAXNF     33024   // >= 32765, padded

// Scratch (no cudaMalloc allowed): per-frame params.
// g_params[f] = {scale (<0 means invalid/unvoiced), new_len as float}
__device__ float2 g_params[MAXNF];

__global__ void psola_init_kernel(const float* __restrict__ src_f0,
                                  const float* __restrict__ tgt_f0,
                                  const int* __restrict__ voiced,
                                  int nf)
{
    int i = blockIdx.x * blockDim.x + threadIdx.x;
    if (i < nf) {
        float s = src_f0[i];
        float t = tgt_f0[i];
        bool valid = (voiced[i] != 0) && (s >= 1.0f) && (t >= 1.0f);
        float denom = (t >= 1.0f) ? t : 1.0f;
        float ratio = fminf(fmaxf(s / denom, 0.25f), 4.0f);
        // jnp.round is round-half-to-even -> rintf (device default RN mode)
        float nl = fmaxf(1.0f, rintf((float)FRAME_L * ratio));
        float scale = (float)FRAME_L / nl;
        float2 p;
        p.x = valid ? scale : -1.0f;
        p.y = nl;
        g_params[i] = p;
    }
}

// Each thread produces 4 consecutive output samples (aligned float4).
// The 4 samples share the same covering-frame set {fmax-0..fmax-3}.
//
// Hann weights computed, not loaded:
//   h(j + 256k) = 0.5 - 0.5*cos(theta_j + k*pi/2)
//   k=0: 0.5-0.5c   k=1: 0.5+0.5s   k=2: 0.5+0.5c   k=3: 0.5-0.5s
// One fast __sincosf at theta_0 = 2*pi*jb/1024; neighbor samples i=1..3 via
// angle addition with compile-time sin/cos of i*2*pi/1024 (pure FMA).
__global__ void __launch_bounds__(256)
psola_main_kernel(const float* __restrict__ wav,
                  float* __restrict__ out,
                  int T, int nf)
{
    int t4 = (blockIdx.x * blockDim.x + threadIdx.x) << 2;
    if (t4 >= T) return;

    float4 wt4 = *reinterpret_cast<const float4*>(wav + t4);
    float wt[4] = {wt4.x, wt4.y, wt4.z, wt4.w};

    int fmax = t4 >> 8;          // floor(t/HOP)
    int jb   = t4 & 255;         // t mod HOP

    // Per-frame params (warp-uniform-ish -> broadcast loads).
    float scale_k[4], nlen_k[4];
    bool  inr[4], voiced_k[4];
    #pragma unroll
    for (int k = 0; k < 4; k++) {
        int f = fmax - k;
        inr[k] = (f >= 0) & (f < nf);
        float2 p = inr[k] ? g_params[f] : make_float2(-1.0f, 1.0f);
        voiced_k[k] = (p.x >= 0.0f);
        scale_k[k]  = p.x;
        nlen_k[k]   = p.y;
    }

    // Base sincos via fast MUFU intrinsic, then angle addition for i=1..3.
    const float TWO_PI_OVER_L = 6.28318530717958647692f / (float)FRAME_L;
    // Compile-time constants sin/cos(i * 2*pi/1024):
    const float SD1 = 0.0061358846491544753f, CD1 = 0.9999811752826011f;
    const float SD2 = 0.0122715382857199261f, CD2 = 0.9999247018391445f;
    const float SD3 = 0.0184067299058048209f, CD3 = 0.9998305817958234f;

    float s0, c0;
    __sincosf((float)jb * TWO_PI_OVER_L, &s0, &c0);
    float s[4], c[4];
    s[0] = s0;                          c[0] = c0;
    s[1] = fmaf(s0, CD1,  c0 * SD1);    c[1] = fmaf(c0, CD1, -s0 * SD1);
    s[2] = fmaf(s0, CD2,  c0 * SD2);    c[2] = fmaf(c0, CD2, -s0 * SD2);
    s[3] = fmaf(s0, CD3,  c0 * SD3);    c[3] = fmaf(c0, CD3, -s0 * SD3);

    float acc[4] = {0.f, 0.f, 0.f, 0.f};
    float ws[4]  = {0.f, 0.f, 0.f, 0.f};

    #pragma unroll
    for (int k = 0; k < 4; k++) {
        if (!inr[k]) continue;
        const float* __restrict__ fr = wav + ((fmax - k) << 8);
        int   j0    = jb + (k << 8);
        float scale = scale_k[k];
        float nlen  = nlen_k[k];
        bool  vo    = voiced_k[k];

        #pragma unroll
        for (int i = 0; i < 4; i++) {
            // hann weight from (s[i], c[i]) with folded signs per k
            float hw;
            if      (k == 0) hw = fmaf(-0.5f, c[i], 0.5f);
            else if (k == 1) hw = fmaf( 0.5f, s[i], 0.5f);
            else if (k == 2) hw = fmaf( 0.5f, c[i], 0.5f);
            else             hw = fmaf(-0.5f, s[i], 0.5f);
            ws[i] += hw;

            float cv;
            if (!vo) {
                cv = wt[i];         // passthrough: frames[f][j] == wav[t]
            } else {
                int j = j0 + i;
                float x  = fminf(fmaxf(fmaf((float)j + 0.5f, scale, -0.5f), 0.0f),
                                 (float)(FRAME_L - 1));
                int   x0 = __float2int_rd(x);
                float w  = x - (float)x0;
                int   x1 = min(x0 + 1, FRAME_L - 1);
                float a  = __ldg(fr + x0);
                float b  = __ldg(fr + x1);
                float v  = fmaf(b - a, w, a);   // a*(1-w)+b*w
                cv = ((float)j < nlen) ? v : 0.0f;
            }
            acc[i] = fmaf(cv, hw, acc[i]);
        }
    }

    float4 r;
    r.x = (ws[0] > 1e-8f) ? acc[0] / ws[0] : acc[0];
    r.y = (ws[1] > 1e-8f) ? acc[1] / ws[1] : acc[1];
    r.z = (ws[2] > 1e-8f) ? acc[2] / ws[2] : acc[2];
    r.w = (ws[3] > 1e-8f) ? acc[3] / ws[3] : acc[3];
    *reinterpret_cast<float4*>(out + t4) = r;
}

extern "C" void kernel_launch(void* const* d_in, const int* in_sizes, int n_in,
                              void* d_out, int out_size)
{
    const float* wav    = (const float*)d_in[0];
    const float* src_f0 = (const float*)d_in[1];
    const float* tgt_f0 = (const float*)d_in[2];
    const int*   voiced = (const int*)d_in[3];
    float* out = (float*)d_out;

    int T  = in_sizes[0];
    int nf_cap = (T - FRAME_L) / HOP + 1;
    int nf = in_sizes[1] < nf_cap ? in_sizes[1] : nf_cap;
    if (nf > MAXNF) nf = MAXNF;

    {
        int threads = 256;
        int blocks = (nf + threads - 1) / threads;
        psola_init_kernel<<<blocks, threads>>>(src_f0, tgt_f0, voiced, nf);
    }
    {
        int threads = 256;
        int n4 = (T + 3) / 4;
        int blocks = (n4 + threads - 1) / threads;
        psola_main_kernel<<<blocks, threads>>>(wav, out, T, nf);
    }
}

// round 5
// speedup vs baseline: 1.7007x; 1.7007x over previous
#include <cuda_runtime.h>
#include <cuda_bf16.h>

#define FRAME_L   1024
#define HOP       256
#define MAXNF     33024   // >= 32765, padded

// Scratch (no cudaMalloc allowed): per-frame params + hann table.
// g_params[f] = {scale (<0 means invalid/unvoiced), new_len as float}
__device__ float2 g_params[MAXNF];
__device__ __align__(16) float g_hann[FRAME_L];

__global__ void psola_init_kernel(const float* __restrict__ src_f0,
                                  const float* __restrict__ tgt_f0,
                                  const int* __restrict__ voiced,
                                  int nf)
{
    int i = blockIdx.x * blockDim.x + threadIdx.x;
    if (i < FRAME_L) {
        g_hann[i] = 0.5f - 0.5f * cosf(6.28318530717958647692f * (float)i / (float)FRAME_L);
    }
    if (i < nf) {
        float s = src_f0[i];
        float t = tgt_f0[i];
        bool valid = (voiced[i] != 0) && (s >= 1.0f) && (t >= 1.0f);
        float denom = (t >= 1.0f) ? t : 1.0f;
        float ratio = fminf(fmaxf(s / denom, 0.25f), 4.0f);
        // jnp.round is round-half-to-even -> rintf (device default RN mode)
        float nl = fmaxf(1.0f, rintf((float)FRAME_L * ratio));
        float scale = (float)FRAME_L / nl;
        float2 p;
        p.x = valid ? scale : -1.0f;
        p.y = nl;
        g_params[i] = p;
    }
}

// Each thread produces 4 consecutive output samples (aligned float4).
// The 4 samples share the same covering-frame set {fmax-0..fmax-3}.
// Interior samples (all 4 frames present): sum of the 4 quadrature hann
// phases is exactly 2.0 -> normalize by *0.5f, no ws accumulation, no fdiv.
__global__ void __launch_bounds__(256)
psola_main_kernel(const float* __restrict__ wav,
                  float* __restrict__ out,
                  int T, int nf)
{
    int t4 = (blockIdx.x * blockDim.x + threadIdx.x) << 2;
    if (t4 >= T) return;

    float4 wt4 = *reinterpret_cast<const float4*>(wav + t4);
    float wt[4] = {wt4.x, wt4.y, wt4.z, wt4.w};

    int fmax = t4 >> 8;          // floor(t/HOP); same for all 4 samples
    int jb   = t4 & 255;         // t mod HOP (multiple of 4)

    bool interior = (fmax >= 3) & (fmax <= nf - 1);

    float acc[4] = {0.f, 0.f, 0.f, 0.f};
    float ws[4]  = {0.f, 0.f, 0.f, 0.f};   // used only on edge path

    #pragma unroll
    for (int k = 0; k < 4; k++) {
        int f = fmax - k;
        if (!interior) {
            if (f < 0 || f >= nf) continue;
        }

        float2 p = g_params[f];
        const float* __restrict__ fr = wav + (f << 8);   // frame start = f*HOP
        int   j0    = jb + (k << 8);                     // in [0, 1024), 4-aligned
        bool  vo    = (p.x >= 0.0f);
        float scale = p.x;
        float nlen  = p.y;

        // 4 contiguous hann weights in one 128-bit load
        float4 h4 = *reinterpret_cast<const float4*>(g_hann + j0);
        float hk[4] = {h4.x, h4.y, h4.z, h4.w};

        #pragma unroll
        for (int i = 0; i < 4; i++) {
            float hw = hk[i];
            if (!interior) ws[i] += hw;

            float c;
            if (!vo) {
                c = wt[i];          // passthrough: frames[f][j] == wav[t]
            } else {
                int j = j0 + i;
                float x  = fminf(fmaxf(fmaf((float)j + 0.5f, scale, -0.5f), 0.0f),
                                 (float)(FRAME_L - 1));
                int   x0 = __float2int_rd(x);
                float w  = x - (float)x0;
                int   x1 = min(x0 + 1, FRAME_L - 1);
                float a  = __ldg(fr + x0);
                float b  = __ldg(fr + x1);
                float v  = fmaf(b - a, w, a);   // a*(1-w)+b*w
                c = ((float)j < nlen) ? v : 0.0f;
            }
            acc[i] = fmaf(c, hw, acc[i]);
        }
    }

    float4 r;
    if (interior) {
        // Sum of the 4 hann quadrature phases is exactly 2.0
        r.x = acc[0] * 0.5f;
        r.y = acc[1] * 0.5f;
        r.z = acc[2] * 0.5f;
        r.w = acc[3] * 0.5f;
    } else {
        r.x = (ws[0] > 1e-8f) ? acc[0] / ws[0] : acc[0];
        r.y = (ws[1] > 1e-8f) ? acc[1] / ws[1] : acc[1];
        r.z = (ws[2] > 1e-8f) ? acc[2] / ws[2] : acc[2];
        r.w = (ws[3] > 1e-8f) ? acc[3] / ws[3] : acc[3];
    }
    *reinterpret_cast<float4*>(out + t4) = r;
}

extern "C" void kernel_launch(void* const* d_in, const int* in_sizes, int n_in,
                              void* d_out, int out_size)
{
    const float* wav    = (const float*)d_in[0];
    const float* src_f0 = (const float*)d_in[1];
    const float* tgt_f0 = (const float*)d_in[2];
    const int*   voiced = (const int*)d_in[3];
    float* out = (float*)d_out;

    int T  = in_sizes[0];
    int nf_cap = (T - FRAME_L) / HOP + 1;
    int nf = in_sizes[1] < nf_cap ? in_sizes[1] : nf_cap;
    if (nf > MAXNF) nf = MAXNF;

    {
        int work = nf > FRAME_L ? nf : FRAME_L;
        int threads = 256;
        int blocks = (work + threads - 1) / threads;
        psola_init_kernel<<<blocks, threads>>>(src_f0, tgt_f0, voiced, nf);
    }
    {
        int threads = 256;
        int n4 = (T + 3) / 4;
        int blocks = (n4 + threads - 1) / threads;
        psola_main_kernel<<<blocks, threads>>>(wav, out, T, nf);
    }
}

// round 6
// speedup vs baseline: 1.7138x; 1.0077x over previous
#include <cuda_runtime.h>
#include <cuda_bf16.h>

#define FRAME_L   1024
#define HOP       256
#define MAXNF     33024   // >= 32765, padded

// Scratch (no cudaMalloc allowed): per-frame params + hann table.
// g_params[f] = {scale (<0 means invalid/unvoiced), new_len as float}
__device__ float2 g_params[MAXNF];
__device__ __align__(16) float g_hann[FRAME_L];

__global__ void psola_init_kernel(const float* __restrict__ src_f0,
                                  const float* __restrict__ tgt_f0,
                                  const int* __restrict__ voiced,
                                  int nf)
{
    int i = blockIdx.x * blockDim.x + threadIdx.x;
    if (i < FRAME_L) {
        g_hann[i] = 0.5f - 0.5f * cosf(6.28318530717958647692f * (float)i / (float)FRAME_L);
    }
    if (i < nf) {
        float s = src_f0[i];
        float t = tgt_f0[i];
        bool valid = (voiced[i] != 0) && (s >= 1.0f) && (t >= 1.0f);
        float denom = (t >= 1.0f) ? t : 1.0f;
        float ratio = fminf(fmaxf(s / denom, 0.25f), 4.0f);
        // jnp.round is round-half-to-even -> rintf (device default RN mode)
        float nl = fmaxf(1.0f, rintf((float)FRAME_L * ratio));
        float scale = (float)FRAME_L / nl;
        float2 p;
        p.x = valid ? scale : -1.0f;
        p.y = nl;
        g_params[i] = p;
    }
}

// Each thread produces 4 consecutive output samples (aligned float4).
// The 4 samples share the same covering-frame set {fmax-0..fmax-3}.
// Interior samples: the 4 quadrature hann phases sum to exactly 2.0
//   -> normalize by *0.5f (no ws accumulation, no fdiv).
// Gather trick: x0 = min(floor(x), 1022), b loaded at [addr+4] (immediate
// offset, no second wide-IMAD). For x == 1023.0 this gives w=1 -> fr[1023],
// identical to the reference's x0=1023/w=0 path.
__global__ void __launch_bounds__(256)
psola_main_kernel(const float* __restrict__ wav,
                  float* __restrict__ out,
                  int T, int nf)
{
    int t4 = (blockIdx.x * blockDim.x + threadIdx.x) << 2;
    if (t4 >= T) return;

    float4 wt4 = *reinterpret_cast<const float4*>(wav + t4);
    float wt[4] = {wt4.x, wt4.y, wt4.z, wt4.w};

    int fmax = t4 >> 8;          // floor(t/HOP); same for all 4 samples
    int jb   = t4 & 255;         // t mod HOP (multiple of 4)

    bool interior = (fmax >= 3) & (fmax <= nf - 1);

    float acc[4] = {0.f, 0.f, 0.f, 0.f};
    float ws[4]  = {0.f, 0.f, 0.f, 0.f};   // edge path only

    #pragma unroll
    for (int k = 0; k < 4; k++) {
        int f = fmax - k;
        if (!interior) {
            if (f < 0 || f >= nf) continue;
        }

        float2 p = g_params[f];
        const float* __restrict__ fr = wav + (f << 8);   // frame start = f*HOP
        int   j0    = jb + (k << 8);                     // in [0,1024), 4-aligned
        bool  vo    = (p.x >= 0.0f);
        float scale = p.x;

        // Hoisted per-frame values
        float jf0 = (float)j0;                 // exact
        float rem = p.y - jf0;                 // nlen - j0, exact (ints < 2^24)
        float cc  = fmaf(0.5f, scale, -0.5f);  // 0.5*scale - 0.5

        // 4 contiguous hann weights in one 128-bit load
        float4 h4 = *reinterpret_cast<const float4*>(g_hann + j0);
        float hk[4] = {h4.x, h4.y, h4.z, h4.w};

        #pragma unroll
        for (int i = 0; i < 4; i++) {
            float hw = hk[i];
            if (!interior) ws[i] += hw;

            float c;
            if (!vo) {
                c = wt[i];          // passthrough: frames[f][j] == wav[t]
            } else {
                float jf = jf0 + (float)i;     // exact
                float x  = fminf(fmaxf(fmaf(jf, scale, cc), 0.0f),
                                 (float)(FRAME_L - 1));
                int   x0 = min(__float2int_rd(x), FRAME_L - 2);
                float w  = x - (float)x0;
                float a  = __ldg(fr + x0);
                float b  = __ldg(fr + x0 + 1);   // immediate +4B offset
                float v  = fmaf(b - a, w, a);
                c = ((float)i < rem) ? v : 0.0f;
            }
            acc[i] = fmaf(c, hw, acc[i]);
        }
    }

    float4 r;
    if (interior) {
        r.x = acc[0] * 0.5f;
        r.y = acc[1] * 0.5f;
        r.z = acc[2] * 0.5f;
        r.w = acc[3] * 0.5f;
    } else {
        r.x = (ws[0] > 1e-8f) ? acc[0] / ws[0] : acc[0];
        r.y = (ws[1] > 1e-8f) ? acc[1] / ws[1] : acc[1];
        r.z = (ws[2] > 1e-8f) ? acc[2] / ws[2] : acc[2];
        r.w = (ws[3] > 1e-8f) ? acc[3] / ws[3] : acc[3];
    }
    *reinterpret_cast<float4*>(out + t4) = r;
}

extern "C" void kernel_launch(void* const* d_in, const int* in_sizes, int n_in,
                              void* d_out, int out_size)
{
    const float* wav    = (const float*)d_in[0];
    const float* src_f0 = (const float*)d_in[1];
    const float* tgt_f0 = (const float*)d_in[2];
    const int*   voiced = (const int*)d_in[3];
    float* out = (float*)d_out;

    int T  = in_sizes[0];
    int nf_cap = (T - FRAME_L) / HOP + 1;
    int nf = in_sizes[1] < nf_cap ? in_sizes[1] : nf_cap;
    if (nf > MAXNF) nf = MAXNF;

    {
        int work = nf > FRAME_L ? nf : FRAME_L;
        int threads = 256;
        int blocks = (work + threads - 1) / threads;
        psola_init_kernel<<<blocks, threads>>>(src_f0, tgt_f0, voiced, nf);
    }
    {
        int threads = 256;
        int n4 = (T + 3) / 4;
        int blocks = (n4 + threads - 1) / threads;
        psola_main_kernel<<<blocks, threads>>>(wav, out, T, nf);
    }
}